// round 7
// baseline (speedup 1.0000x reference)
#include <cuda_runtime.h>
#include <math_constants.h>
#include <cstdint>

#define NN    10000   // nodes
#define D     128     // feature dim
#define TOPK  8
#define DEG   32
#define OUTCH 128
#define INCH  9       // K+1
#define KS    9       // kernel size
#define XOUT  120     // D - K

// Prepacked weight pairs for packed-f32x2 conv:
//   k=0..4 (even-x set):  (w_{2k}, w_{2k+1}) with w9 := 0
//   k=5..9 (odd-x  set):  j=k-5: j==0 -> (0, w0) ; else (w_{2j-1}, w_{2j})
// Layout [c][k][o]: a warp's 32 consecutive o read 256B contiguous (L1-hot).
__device__ float2 g_wpre[INCH][10][OUTCH];

__global__ void prep_weights_kernel(const float* __restrict__ cw)
{
    int idx = blockIdx.x * blockDim.x + threadIdx.x;
    if (idx >= INCH * 10 * OUTCH) return;
    int o = idx % OUTCH;
    int k = (idx / OUTCH) % 10;
    int c = idx / (OUTCH * 10);
    const float* w = cw + (size_t)o * (INCH * KS) + c * KS;   // w[0..8]
    float2 v;
    if (k < 5) {
        v.x = w[2 * k];
        v.y = (2 * k + 1 < KS) ? w[2 * k + 1] : 0.0f;
    } else {
        int j = k - 5;
        if (j == 0) { v.x = 0.0f;          v.y = w[0];     }
        else        { v.x = w[2 * j - 1];  v.y = w[2 * j]; }
    }
    g_wpre[c][k][o] = v;
}

__device__ __forceinline__ unsigned long long ffma2(unsigned long long a,
                                                    unsigned long long b,
                                                    unsigned long long c)
{
    unsigned long long d;
    asm("fma.rn.f32x2 %0, %1, %2, %3;" : "=l"(d) : "l"(a), "l"(b), "l"(c));
    return d;
}

__device__ __forceinline__ void bar_sync(int id, int count)
{
    asm volatile("bar.sync %0, %1;" :: "r"(id), "r"(count) : "memory");
}

// Persistent warp-specialized kernel:
//   threads 0..127  : conv consumers (o = tid)
//   threads 128..255: producers (adjacency scan + gather + top-8 -> sel[buf])
// Ping-pong on named barriers 1 (buf 0) and 2 (buf 1), count 256.
// Producer-internal sync uses named barrier 3, count 128.
__global__ __launch_bounds__(256, 2)
void lgcl_pipe_kernel(const float* __restrict__ nf,
                      const int*   __restrict__ adj,
                      const float* __restrict__ cb,
                      float*       __restrict__ out)
{
    __shared__ __align__(16) float sel[2][INCH][D];
    __shared__ int s_nbr[DEG];
    __shared__ int s_cnt;

    const int tid = threadIdx.x;

    if (tid >= 128) {
        // ======================= PRODUCER =======================
        const int ptid = tid - 128;          // 0..127
        int buf = 0;
        for (int n = blockIdx.x; n < NN; n += gridDim.x, buf ^= 1) {
            // -- reset count --
            if (ptid == 0) s_cnt = 0;
            bar_sync(3, 128);

            // -- scan dense adjacency row, compact neighbor indices --
            {
                const int4* row4 = reinterpret_cast<const int4*>(adj + (size_t)n * NN);
                for (int i = ptid; i < NN / 4; i += 128) {
                    int4 v = row4[i];
                    if (v.x | v.y | v.z | v.w) {
                        if (v.x) s_nbr[atomicAdd(&s_cnt, 1)] = 4 * i + 0;
                        if (v.y) s_nbr[atomicAdd(&s_cnt, 1)] = 4 * i + 1;
                        if (v.z) s_nbr[atomicAdd(&s_cnt, 1)] = 4 * i + 2;
                        if (v.w) s_nbr[atomicAdd(&s_cnt, 1)] = 4 * i + 3;
                    }
                }
            }
            bar_sync(3, 128);
            const int m = s_cnt;             // <= 32

            // -- per-feature-column top-8 (d = ptid) --
            {
                const int d = ptid;
                float tk[TOPK];
                #pragma unroll
                for (int s = 0; s < TOPK; s++) tk[s] = -CUDART_INF_F;

                #pragma unroll
                for (int j0 = 0; j0 < DEG; j0 += 8) {
                    float v[8];
                    #pragma unroll
                    for (int u = 0; u < 8; u++) {
                        int j = j0 + u;
                        v[u] = (j < m) ? nf[(size_t)s_nbr[j] * D + d] : -CUDART_INF_F;
                    }
                    #pragma unroll
                    for (int u = 0; u < 8; u++) {
                        float x = v[u];
                        #pragma unroll
                        for (int s = 0; s < TOPK; s++) {
                            float hi = fmaxf(tk[s], x);
                            x        = fminf(tk[s], x);
                            tk[s]    = hi;
                        }
                    }
                }
                // torch zero-pads missing neighbors before topk
                for (int z = m; z < TOPK; z++) {
                    float x = 0.0f;
                    #pragma unroll
                    for (int s = 0; s < TOPK; s++) {
                        float hi = fmaxf(tk[s], x);
                        x        = fminf(tk[s], x);
                        tk[s]    = hi;
                    }
                }

                sel[buf][0][d] = nf[(size_t)n * D + d];
                #pragma unroll
                for (int s = 0; s < TOPK; s++) sel[buf][1 + s][d] = tk[s];
            }

            // hand off buffer to consumers (also serves as consumed-ack
            // for this buffer's previous use, via rendezvous semantics)
            bar_sync(1 + buf, 256);
        }
    } else {
        // ======================= CONSUMER (conv) =======================
        const int o = tid;                   // output channel
        const float bias = cb[o];
        int buf = 0;
        for (int n = blockIdx.x; n < NN; n += gridDim.x, buf ^= 1) {
            bar_sync(1 + buf, 256);          // wait: sel[buf] ready

            float* op = out + ((size_t)n * OUTCH + o) * XOUT;

            for (int cb0 = 0; cb0 < XOUT; cb0 += 24) {     // 5 chunks of 24 x
                unsigned long long acc[24];
                #pragma unroll
                for (int u = 0; u < 24; u++) acc[u] = 0ull;

                for (int c = 0; c < INCH; c++) {
                    unsigned long long W[10];
                    #pragma unroll
                    for (int k = 0; k < 10; k++)
                        W[k] = *reinterpret_cast<const unsigned long long*>(&g_wpre[c][k][o]);

                    const unsigned long long* Prow =
                        reinterpret_cast<const unsigned long long*>(&sel[buf][c][0]);

                    #pragma unroll
                    for (int g = 0; g < 24; g += 8) {      // 8 x = 4 x-pairs
                        const int e0 = (cb0 + g) >> 1;
                        unsigned long long P[8];
                        #pragma unroll
                        for (int i = 0; i < 8; i++) P[i] = Prow[e0 + i];
                        #pragma unroll
                        for (int j = 0; j < 4; j++) {
                            #pragma unroll
                            for (int k = 0; k < 5; k++) {
                                acc[g + 2 * j]     = ffma2(P[j + k], W[k],     acc[g + 2 * j]);
                                acc[g + 2 * j + 1] = ffma2(P[j + k], W[5 + k], acc[g + 2 * j + 1]);
                            }
                        }
                    }
                }

                #pragma unroll
                for (int u = 0; u < 24; u += 4) {
                    float2 a0 = *reinterpret_cast<float2*>(&acc[u + 0]);
                    float2 a1 = *reinterpret_cast<float2*>(&acc[u + 1]);
                    float2 a2 = *reinterpret_cast<float2*>(&acc[u + 2]);
                    float2 a3 = *reinterpret_cast<float2*>(&acc[u + 3]);
                    float4 r = make_float4(a0.x + a0.y + bias,
                                           a1.x + a1.y + bias,
                                           a2.x + a2.y + bias,
                                           a3.x + a3.y + bias);
                    *reinterpret_cast<float4*>(op + cb0 + u) = r;
                }
            }
        }
    }
}

extern "C" void kernel_launch(void* const* d_in, const int* in_sizes, int n_in,
                              void* d_out, int out_size)
{
    const float* nf  = (const float*)d_in[0];   // [10000, 128]
    const int*   adj = (const int*)  d_in[1];   // [10000, 10000]
    const float* cw  = (const float*)d_in[2];   // [128, 9, 9]
    const float* cb  = (const float*)d_in[3];   // [128]
    float*       out = (float*)d_out;           // [10000, 128, 120]

    prep_weights_kernel<<<(INCH * 10 * OUTCH + 127) / 128, 128>>>(cw);
    lgcl_pipe_kernel<<<296, 256>>>(nf, adj, cb, out);
}